// round 15
// baseline (speedup 1.0000x reference)
#include <cuda_runtime.h>
#include <cuda_bf16.h>
#include <math.h>
#include <stdint.h>

// ---------------------------------------------------------------------------
// SelectiveSSM (Mamba block) — pre-split bf16 hi/lo operands + 2-stage
// cp.async mma.sync GEMMs (128x64 tile, 2 CTA/SM, term-reordered MMAs)
// + smem-staged selective scan.
// B=2, L=1024, D_MODEL=1024, D_INNER=2048, D_STATE=16, DT_RANK=64, D_CONV=4
// ---------------------------------------------------------------------------

#define BATCH   2
#define SEQ     1024
#define DMODEL  1024
#define DINNER  2048
#define DSTATE  16
#define DTRANK  64
#define DCONV   4
#define MROWS   (BATCH * SEQ)          // 2048
#define XPITCH  128                    // padded x_dbl width (logical 96)

// -------------------- fp32 scratch -----------------------------------------
__device__ float g_xz[MROWS * 2 * DINNER];     // [2048, 4096]
__device__ float g_xconv[MROWS * DINNER];      // [2048, 2048]
__device__ float g_zsilu[MROWS * DINNER];      // [2048, 2048]
__device__ float g_xdbl[MROWS * XPITCH];       // [2048, 128] (cols 96.. = 0)
__device__ float g_dt[MROWS * DINNER];         // [2048, 2048]

// -------------------- bf16 hi/lo planes ------------------------------------
__device__ __nv_bfloat16 g_xhi[MROWS * DMODEL],   g_xlo[MROWS * DMODEL];
__device__ __nv_bfloat16 g_Wih[2 * DINNER * DMODEL], g_Wil[2 * DINNER * DMODEL];
__device__ __nv_bfloat16 g_xch[MROWS * DINNER],   g_xcl[MROWS * DINNER];
__device__ __nv_bfloat16 g_Wxh[XPITCH * DINNER],  g_Wxl[XPITCH * DINNER];
__device__ __nv_bfloat16 g_xdh[MROWS * XPITCH],   g_xdl[MROWS * XPITCH];
__device__ __nv_bfloat16 g_Wdh[DINNER * DTRANK],  g_Wdl[DINNER * DTRANK];
__device__ __nv_bfloat16 g_yh[MROWS * DINNER],    g_yl[MROWS * DINNER];
__device__ __nv_bfloat16 g_Woh[DMODEL * DINNER],  g_Wol[DMODEL * DINNER];

// ===================== PTX helpers (sm_80+ only) ===========================
__device__ __forceinline__ uint32_t smem_u32(const void* p) {
    uint32_t a;
    asm("{ .reg .u64 t; cvta.to.shared.u64 t, %1; cvt.u32.u64 %0, t; }"
        : "=r"(a) : "l"(p));
    return a;
}
__device__ __forceinline__ void ldsm_x4(uint32_t* r, uint32_t addr) {
    asm volatile("ldmatrix.sync.aligned.m8n8.x4.shared.b16 {%0,%1,%2,%3}, [%4];"
        : "=r"(r[0]), "=r"(r[1]), "=r"(r[2]), "=r"(r[3]) : "r"(addr));
}
__device__ __forceinline__ void ldsm_x2(uint32_t* r, uint32_t addr) {
    asm volatile("ldmatrix.sync.aligned.m8n8.x2.shared.b16 {%0,%1}, [%2];"
        : "=r"(r[0]), "=r"(r[1]) : "r"(addr));
}
__device__ __forceinline__ void mma16816(float* c, const uint32_t* a,
                                         const uint32_t* b) {
    asm volatile("mma.sync.aligned.m16n8k16.row.col.f32.bf16.bf16.f32 "
        "{%0,%1,%2,%3}, {%4,%5,%6,%7}, {%8,%9}, {%0,%1,%2,%3};"
        : "+f"(c[0]), "+f"(c[1]), "+f"(c[2]), "+f"(c[3])
        : "r"(a[0]), "r"(a[1]), "r"(a[2]), "r"(a[3]), "r"(b[0]), "r"(b[1]));
}
#define CPA16(dst, src) \
    asm volatile("cp.async.cg.shared.global [%0], [%1], 16;" \
                 :: "r"(dst), "l"(src) : "memory")
#define CPA4(dst, src) \
    asm volatile("cp.async.ca.shared.global [%0], [%1], 4;" \
                 :: "r"(dst), "l"(src) : "memory")
#define CP_COMMIT() asm volatile("cp.async.commit_group;" ::: "memory")

// ---------------------------------------------------------------------------
// Tensor-core GEMM on pre-split operands (3-term Markidis split).
// CTA tile 128x64, BK=32, 256 threads (8 warps: 4m x 2n, warptile 32x32).
// 2-stage cp.async double buffer (compile-time parity). blockIdx.z = split-K.
// MMA terms issued as all-hh, all-hl, all-lh (accumulator RAW distance 8).
// EPI: 0 = plain store, 1 = softplus(acc+bias) store, 2 = atomicAdd.
// ---------------------------------------------------------------------------
#define BMT   128
#define BNT   64
#define BKT   32
#define PITCH 40
#define A_PLANE 10240u   // 128*40*2 bytes
#define B_PLANE 5120u    // 64*40*2 bytes
#define GSMEM   61440    // 2 bufs * 2 planes * (A_PLANE + B_PLANE)

__device__ __forceinline__ void cpa_fill(
    uint32_t sAh, uint32_t sAl, uint32_t sBh, uint32_t sBl,
    const __nv_bfloat16* Ahi, const __nv_bfloat16* Alo, int lda,
    const __nv_bfloat16* Whi, const __nv_bfloat16* Wlo, int ldw,
    int row0, int col0, int k0, int tid)
{
#pragma unroll
    for (int it = 0; it < 2; it++) {
        int idx = it * 256 + tid;
        int r = idx >> 2, ch = idx & 3;
        const size_t aoff = (size_t)(row0 + r) * lda + k0 + ch * 8;
        const uint32_t sd = (uint32_t)(r * 80 + ch * 16);
        CPA16(sAh + sd, Ahi + aoff);
        CPA16(sAl + sd, Alo + aoff);
    }
    {
        int r = tid >> 2, ch = tid & 3;
        const size_t boff = (size_t)(col0 + r) * ldw + k0 + ch * 8;
        const uint32_t sd = (uint32_t)(r * 80 + ch * 16);
        CPA16(sBh + sd, Whi + boff);
        CPA16(sBl + sd, Wlo + boff);
    }
    CP_COMMIT();
}

template<int EPI>
__global__ __launch_bounds__(256, 2)
void gemm_mma(const __nv_bfloat16* __restrict__ Ahi,
              const __nv_bfloat16* __restrict__ Alo, int lda,
              const __nv_bfloat16* __restrict__ Whi,
              const __nv_bfloat16* __restrict__ Wlo, int ldw,
              const float* __restrict__ bias,
              float* __restrict__ C, int ldc, int K)
{
    extern __shared__ char smem[];
    const uint32_t sb = smem_u32(smem);
    const uint32_t aB[2][2] = {{sb, sb + A_PLANE},
                               {sb + 2 * A_PLANE, sb + 3 * A_PLANE}};
    const uint32_t bB[2][2] = {{sb + 4 * A_PLANE, sb + 4 * A_PLANE + B_PLANE},
                               {sb + 4 * A_PLANE + 2 * B_PLANE,
                                sb + 4 * A_PLANE + 3 * B_PLANE}};

    const int tid  = threadIdx.x;
    const int lane = tid & 31;
    const int wid  = tid >> 5;
    const int wm   = wid >> 1;           // 0..3
    const int wn   = wid & 1;            // 0..1
    const int row0 = blockIdx.y * BMT;
    const int col0 = blockIdx.x * BNT;
    const int kbase = blockIdx.z * K;    // split-K chunk base

    const int a_r = lane & 15, a_k = (lane >> 4) << 3;
    const int b_r = lane & 7,  b_k = ((lane >> 3) & 1) << 3;

    float acc[2][4][4];
#pragma unroll
    for (int mi = 0; mi < 2; mi++)
#pragma unroll
        for (int ni = 0; ni < 4; ni++)
#pragma unroll
            for (int j = 0; j < 4; j++) acc[mi][ni][j] = 0.f;

    const int nit = K / BKT;
    cpa_fill(aB[0][0], aB[0][1], bB[0][0], bB[0][1],
             Ahi, Alo, lda, Whi, Wlo, ldw, row0, col0, kbase, tid);

    for (int c = 0; c < nit; c++) {
        const int cur = c & 1;
        if (c + 1 < nit) {
            cpa_fill(aB[cur ^ 1][0], aB[cur ^ 1][1], bB[cur ^ 1][0], bB[cur ^ 1][1],
                     Ahi, Alo, lda, Whi, Wlo, ldw, row0, col0,
                     kbase + (c + 1) * BKT, tid);
            asm volatile("cp.async.wait_group 1;" ::: "memory");
        } else {
            asm volatile("cp.async.wait_group 0;" ::: "memory");
        }
        __syncthreads();

#pragma unroll
        for (int s = 0; s < 2; s++) {
            uint32_t ah[2][4], al[2][4], bh[4][2], bl[4][2];
#pragma unroll
            for (int mi = 0; mi < 2; mi++) {
                uint32_t e = (uint32_t)((wm * 32 + mi * 16 + a_r) * PITCH
                                        + s * 16 + a_k) * 2u;
                ldsm_x4(ah[mi], aB[cur][0] + e);
                ldsm_x4(al[mi], aB[cur][1] + e);
            }
#pragma unroll
            for (int ni = 0; ni < 4; ni++) {
                uint32_t e = (uint32_t)((wn * 32 + ni * 8 + b_r) * PITCH
                                        + s * 16 + b_k) * 2u;
                ldsm_x2(bh[ni], bB[cur][0] + e);
                ldsm_x2(bl[ni], bB[cur][1] + e);
            }
            // term-reordered: same-accumulator reuse distance = 8 MMAs
#pragma unroll
            for (int mi = 0; mi < 2; mi++)
#pragma unroll
                for (int ni = 0; ni < 4; ni++)
                    mma16816(acc[mi][ni], ah[mi], bh[ni]);
#pragma unroll
            for (int mi = 0; mi < 2; mi++)
#pragma unroll
                for (int ni = 0; ni < 4; ni++)
                    mma16816(acc[mi][ni], ah[mi], bl[ni]);
#pragma unroll
            for (int mi = 0; mi < 2; mi++)
#pragma unroll
                for (int ni = 0; ni < 4; ni++)
                    mma16816(acc[mi][ni], al[mi], bh[ni]);
        }
        __syncthreads();
    }

    // ---- epilogue ----
    const int cr = lane >> 2;
    const int cc = (lane & 3) * 2;
#pragma unroll
    for (int mi = 0; mi < 2; mi++) {
#pragma unroll
        for (int ni = 0; ni < 4; ni++) {
            int row = row0 + wm * 32 + mi * 16 + cr;
            int col = col0 + wn * 32 + ni * 8 + cc;
            float v[4] = {acc[mi][ni][0], acc[mi][ni][1],
                          acc[mi][ni][2], acc[mi][ni][3]};
            if (EPI == 1) {
#pragma unroll
                for (int j = 0; j < 4; j++) {
                    float t = v[j] + bias[col + (j & 1)];
                    v[j] = (t > 20.f) ? t : log1pf(__expf(t));
                }
            }
            if (EPI == 2) {
                atomicAdd(C + (size_t)row * ldc + col,           v[0]);
                atomicAdd(C + (size_t)row * ldc + col + 1,       v[1]);
                atomicAdd(C + (size_t)(row + 8) * ldc + col,     v[2]);
                atomicAdd(C + (size_t)(row + 8) * ldc + col + 1, v[3]);
            } else {
                *(float2*)(C + (size_t)row * ldc + col)       = make_float2(v[0], v[1]);
                *(float2*)(C + (size_t)(row + 8) * ldc + col) = make_float2(v[2], v[3]);
            }
        }
    }
}

// -------------------- zero-fill (graph-safe memset replacement) ------------
__global__ void zero_buf(float4* __restrict__ p, int n4)
{
    int i = blockIdx.x * blockDim.x + threadIdx.x;
    if (i < n4) p[i] = make_float4(0.f, 0.f, 0.f, 0.f);
}

// -------------------- fp32 -> bf16 hi/lo converters ------------------------
__global__ void cvt_hl(const float4* __restrict__ in,
                       __nv_bfloat162* __restrict__ hi,
                       __nv_bfloat162* __restrict__ lo, int n4)
{
    int i = blockIdx.x * blockDim.x + threadIdx.x;
    if (i >= n4) return;
    float4 v = in[i];
    float f[4] = {v.x, v.y, v.z, v.w};
    __nv_bfloat16 h[4], l[4];
#pragma unroll
    for (int j = 0; j < 4; j++) {
        h[j] = __float2bfloat16(f[j]);
        l[j] = __float2bfloat16(f[j] - __bfloat162float(h[j]));
    }
    hi[2 * i]     = __nv_bfloat162(h[0], h[1]);
    hi[2 * i + 1] = __nv_bfloat162(h[2], h[3]);
    lo[2 * i]     = __nv_bfloat162(l[0], l[1]);
    lo[2 * i + 1] = __nv_bfloat162(l[2], l[3]);
}

// W_x [96, 2048] -> padded [128, 2048] hi/lo (rows 96..127 zero)
__global__ void cvt_hl_pad_wx(const float* __restrict__ in,
                              __nv_bfloat162* __restrict__ hi,
                              __nv_bfloat162* __restrict__ lo)
{
    int i = blockIdx.x * blockDim.x + threadIdx.x;
    if (i >= XPITCH * DINNER / 4) return;
    int row = i >> 9;
    int col4 = (i & 511) << 2;
    float f[4] = {0.f, 0.f, 0.f, 0.f};
    if (row < 96) {
        float4 v = *(const float4*)(in + (size_t)row * DINNER + col4);
        f[0] = v.x; f[1] = v.y; f[2] = v.z; f[3] = v.w;
    }
    __nv_bfloat16 h[4], l[4];
#pragma unroll
    for (int j = 0; j < 4; j++) {
        h[j] = __float2bfloat16(f[j]);
        l[j] = __float2bfloat16(f[j] - __bfloat162float(h[j]));
    }
    hi[2 * i]     = __nv_bfloat162(h[0], h[1]);
    hi[2 * i + 1] = __nv_bfloat162(h[2], h[3]);
    lo[2 * i]     = __nv_bfloat162(l[0], l[1]);
    lo[2 * i + 1] = __nv_bfloat162(l[2], l[3]);
}

// -------------------- causal conv1d + SiLU + z gate (+ inline split) -------
__global__ void conv_silu_kernel(const float* __restrict__ Wc,   // [DINNER,4]
                                 const float* __restrict__ bc)   // [DINNER]
{
    int i = blockIdx.x * blockDim.x + threadIdx.x;      // over MROWS*DINNER
    if (i >= MROWS * DINNER) return;
    int d = i & (DINNER - 1);
    int m = i >> 11;                                    // b*SEQ + l
    int b = m >> 10;
    int l = m & (SEQ - 1);

    float acc = bc[d];
#pragma unroll
    for (int k = 0; k < DCONV; k++) {
        int lt = l - (DCONV - 1) + k;
        if (lt >= 0)
            acc = fmaf(Wc[d * DCONV + k],
                       g_xz[(size_t)((b << 10) + lt) * (2 * DINNER) + d], acc);
    }
    float xc = acc / (1.f + __expf(-acc));              // silu
    g_xconv[i] = xc;
    __nv_bfloat16 hb = __float2bfloat16(xc);
    g_xch[i] = hb;
    g_xcl[i] = __float2bfloat16(xc - __bfloat162float(hb));

    float zv = g_xz[(size_t)m * (2 * DINNER) + DINNER + d];
    g_zsilu[i] = zv / (1.f + __expf(-zv));
}

// ---------------------------------------------------------------------------
// Selective scan v2 — smem-staged, cp.async double-buffered.
// 256 CTAs x 256 threads. CTA owns 16 channels x 16 states.
// ---------------------------------------------------------------------------
#define SCH 16
#define STT 64
#define NSTAGE (SEQ / STT)   // 16
#define BCP 36               // padded B/C row (floats); 144 B = 9*16 (aligned)

__global__ __launch_bounds__(256)
void scan_kernel(const float* __restrict__ A_log,   // [DINNER,16]
                 const float* __restrict__ Dp)      // [DINNER]
{
    __shared__ alignas(16) float s_dt[2][SCH][STT];
    __shared__ alignas(16) float s_xc[2][SCH][STT];
    __shared__ alignas(16) float s_zs[2][SCH][STT];
    __shared__ alignas(16) float s_bc[2][STT][BCP];

    const int tid = threadIdx.x;
    const int c = tid >> 4;              // channel within CTA (0..15)
    const int n = tid & 15;              // state
    const int chg = blockIdx.x * SCH;    // global channel base (0..4095)
    const int b  = chg >> 11;
    const int d0 = chg & (DINNER - 1);
    const size_t mb = (size_t)b * SEQ;

    const float A  = -__expf(A_log[(d0 + c) * DSTATE + n]);
    const float Dv = Dp[d0 + c];

    const uint32_t u_dt = smem_u32(s_dt), u_xc = smem_u32(s_xc);
    const uint32_t u_zs = smem_u32(s_zs), u_bc = smem_u32(s_bc);

    auto fill = [&](int s, int t0) {
#pragma unroll
        for (int i = 0; i < 4; i++) {
            int idx = i * 256 + tid;
            int ch = idx >> 6, t = idx & 63;
            size_t g = (mb + t0 + t) * DINNER + d0 + ch;
            uint32_t so = (uint32_t)(((s * SCH + ch) * STT + t) * 4);
            CPA4(u_dt + so, g_dt + g);
            CPA4(u_xc + so, g_xconv + g);
            CPA4(u_zs + so, g_zsilu + g);
        }
#pragma unroll
        for (int i = 0; i < 2; i++) {
            int idx = i * 256 + tid;
            int t = idx >> 3, chk = idx & 7;
            const float* src = g_xdbl + (mb + t0 + t) * XPITCH + DTRANK + chk * 4;
            uint32_t dst = u_bc + (uint32_t)(((s * STT + t) * BCP + chk * 4) * 4);
            CPA16(dst, src);
        }
        CP_COMMIT();
    };

    fill(0, 0);
    float h = 0.f;

    for (int st = 0; st < NSTAGE; st++) {
        const int cur = st & 1;
        if (st + 1 < NSTAGE) {
            fill(cur ^ 1, (st + 1) * STT);
            asm volatile("cp.async.wait_group 1;" ::: "memory");
        } else {
            asm volatile("cp.async.wait_group 0;" ::: "memory");
        }
        __syncthreads();

        const int t0 = st * STT;
#pragma unroll 4
        for (int t = 0; t < STT; t++) {
            float dtv = s_dt[cur][c][t];
            float xv  = s_xc[cur][c][t];
            float Bv  = s_bc[cur][t][n];
            float Cv  = s_bc[cur][t][16 + n];
            h = __expf(dtv * A) * h + dtv * Bv * xv;
            float yv = h * Cv;
            yv += __shfl_xor_sync(0xffffffffu, yv, 1);
            yv += __shfl_xor_sync(0xffffffffu, yv, 2);
            yv += __shfl_xor_sync(0xffffffffu, yv, 4);
            yv += __shfl_xor_sync(0xffffffffu, yv, 8);
            if (n == 0) {
                float yo = (yv + xv * Dv) * s_zs[cur][c][t];
                __nv_bfloat16 hb = __float2bfloat16(yo);
                __nv_bfloat16 lb = __float2bfloat16(yo - __bfloat162float(hb));
                size_t o = (mb + t0 + t) * DINNER + d0 + c;
                g_yh[o] = hb;
                g_yl[o] = lb;
            }
        }
        __syncthreads();
    }
}

// -------------------- host launcher ----------------------------------------
extern "C" void kernel_launch(void* const* d_in, const int* in_sizes, int n_in,
                              void* d_out, int out_size)
{
    const float* x      = (const float*)d_in[0];
    const float* W_in   = (const float*)d_in[1];
    const float* W_conv = (const float*)d_in[2];
    const float* b_conv = (const float*)d_in[3];
    const float* W_x    = (const float*)d_in[4];
    const float* W_dt   = (const float*)d_in[5];
    const float* b_dt   = (const float*)d_in[6];
    const float* A_log  = (const float*)d_in[7];
    const float* Dp     = (const float*)d_in[8];
    const float* W_out  = (const float*)d_in[9];
    float* out = (float*)d_out;

    float *p_xz, *p_xdbl, *p_dt;
    cudaGetSymbolAddress((void**)&p_xz,   g_xz);
    cudaGetSymbolAddress((void**)&p_xdbl, g_xdbl);
    cudaGetSymbolAddress((void**)&p_dt,   g_dt);

    __nv_bfloat16 *xhi, *xlo, *Wih, *Wil, *xch, *xcl, *Wxh, *Wxl;
    __nv_bfloat16 *xdh, *xdl, *Wdh, *Wdl, *yh, *yl, *Woh, *Wol;
    cudaGetSymbolAddress((void**)&xhi, g_xhi); cudaGetSymbolAddress((void**)&xlo, g_xlo);
    cudaGetSymbolAddress((void**)&Wih, g_Wih); cudaGetSymbolAddress((void**)&Wil, g_Wil);
    cudaGetSymbolAddress((void**)&xch, g_xch); cudaGetSymbolAddress((void**)&xcl, g_xcl);
    cudaGetSymbolAddress((void**)&Wxh, g_Wxh); cudaGetSymbolAddress((void**)&Wxl, g_Wxl);
    cudaGetSymbolAddress((void**)&xdh, g_xdh); cudaGetSymbolAddress((void**)&xdl, g_xdl);
    cudaGetSymbolAddress((void**)&Wdh, g_Wdh); cudaGetSymbolAddress((void**)&Wdl, g_Wdl);
    cudaGetSymbolAddress((void**)&yh,  g_yh);  cudaGetSymbolAddress((void**)&yl,  g_yl);
    cudaGetSymbolAddress((void**)&Woh, g_Woh); cudaGetSymbolAddress((void**)&Wol, g_Wol);

    cudaFuncSetAttribute(gemm_mma<0>, cudaFuncAttributeMaxDynamicSharedMemorySize, GSMEM);
    cudaFuncSetAttribute(gemm_mma<1>, cudaFuncAttributeMaxDynamicSharedMemorySize, GSMEM);
    cudaFuncSetAttribute(gemm_mma<2>, cudaFuncAttributeMaxDynamicSharedMemorySize, GSMEM);

    const int CT = 256;
    #define CVT(src, dh, dl, n) \
        cvt_hl<<<((n) / 4 + CT - 1) / CT, CT>>>((const float4*)(src), \
            (__nv_bfloat162*)(dh), (__nv_bfloat162*)(dl), (n) / 4)

    // splits needed by GEMM1 (+pad)
    CVT(x,     xhi, xlo, MROWS * DMODEL);
    CVT(W_in,  Wih, Wil, 2 * DINNER * DMODEL);
    cvt_hl_pad_wx<<<(XPITCH * DINNER / 4 + CT - 1) / CT, CT>>>(
        W_x, (__nv_bfloat162*)Wxh, (__nv_bfloat162*)Wxl);

    // 3) xz = x @ W_in^T   [2048, 4096], K=1024
    {
        dim3 grid((2 * DINNER) / BNT, MROWS / BMT, 1);   // 64 x 16
        gemm_mma<0><<<grid, 256, GSMEM>>>(xhi, xlo, DMODEL, Wih, Wil, DMODEL,
                                          nullptr, p_xz, 2 * DINNER, DMODEL);
    }
    // remaining weight splits + zero fills (independent of GEMM1)
    CVT(W_dt,  Wdh, Wdl, DINNER * DTRANK);
    CVT(W_out, Woh, Wol, DMODEL * DINNER);
    zero_buf<<<(MROWS * XPITCH / 4 + CT - 1) / CT, CT>>>(
        (float4*)p_xdbl, MROWS * XPITCH / 4);
    zero_buf<<<(MROWS * DMODEL / 4 + CT - 1) / CT, CT>>>(
        (float4*)out, MROWS * DMODEL / 4);

    // causal conv + silu + z gate (+ xconv hi/lo split fused)
    conv_silu_kernel<<<(MROWS * DINNER + CT - 1) / CT, CT>>>(W_conv, b_conv);

    // x_dbl = x_conv @ W_x^T   [2048, 128(pad)], K=2048, split-K=8 (atomics)
    {
        dim3 grid(XPITCH / BNT, MROWS / BMT, 8);         // 2 x 16 x 8
        gemm_mma<2><<<grid, 256, GSMEM>>>(xch, xcl, DINNER, Wxh, Wxl, DINNER,
                                          nullptr, p_xdbl, XPITCH, DINNER / 8);
    }
    CVT(p_xdbl, xdh, xdl, MROWS * XPITCH);

    // dt = softplus(x_dbl[:, :64] @ W_dt^T + b_dt)   [2048, 2048], K=64
    {
        dim3 grid(DINNER / BNT, MROWS / BMT, 1);         // 32 x 16
        gemm_mma<1><<<grid, 256, GSMEM>>>(xdh, xdl, XPITCH, Wdh, Wdl, DTRANK,
                                          b_dt, p_dt, DINNER, DTRANK);
    }
    // selective scan (+ skip + gate fused, emits bf16 hi/lo directly)
    scan_kernel<<<BATCH * DINNER / SCH, 256>>>(A_log, Dp);

    // out = gated @ W_out^T   [2048, 1024], K=2048, split-K=2 (atomics)
    {
        dim3 grid(DMODEL / BNT, MROWS / BMT, 2);         // 16 x 16 x 2
        gemm_mma<2><<<grid, 256, GSMEM>>>(yh, yl, DINNER, Woh, Wol, DINNER,
                                          nullptr, out, DMODEL, DINNER / 2);
    }
    (void)in_sizes; (void)n_in; (void)out_size;
}

// round 16
// speedup vs baseline: 1.0332x; 1.0332x over previous
#include <cuda_runtime.h>
#include <cuda_bf16.h>
#include <math.h>
#include <stdint.h>

// ---------------------------------------------------------------------------
// SelectiveSSM (Mamba block) — pre-split bf16 hi/lo operands + 2-stage
// cp.async mma.sync GEMMs (128x64 tile, x4 B-loads) + smem-staged scan.
// B=2, L=1024, D_MODEL=1024, D_INNER=2048, D_STATE=16, DT_RANK=64, D_CONV=4
// ---------------------------------------------------------------------------

#define BATCH   2
#define SEQ     1024
#define DMODEL  1024
#define DINNER  2048
#define DSTATE  16
#define DTRANK  64
#define DCONV   4
#define MROWS   (BATCH * SEQ)          // 2048
#define XPITCH  128                    // padded x_dbl width (logical 96)

// -------------------- fp32 scratch -----------------------------------------
__device__ float g_xz[MROWS * 2 * DINNER];     // [2048, 4096]
__device__ float g_xconv[MROWS * DINNER];      // [2048, 2048]
__device__ float g_zsilu[MROWS * DINNER];      // [2048, 2048]
__device__ float g_xdbl[MROWS * XPITCH];       // [2048, 128] (cols 96.. = 0)
__device__ float g_dt[MROWS * DINNER];         // [2048, 2048]

// -------------------- bf16 hi/lo planes ------------------------------------
__device__ __nv_bfloat16 g_xhi[MROWS * DMODEL],   g_xlo[MROWS * DMODEL];
__device__ __nv_bfloat16 g_Wih[2 * DINNER * DMODEL], g_Wil[2 * DINNER * DMODEL];
__device__ __nv_bfloat16 g_xch[MROWS * DINNER],   g_xcl[MROWS * DINNER];
__device__ __nv_bfloat16 g_Wxh[XPITCH * DINNER],  g_Wxl[XPITCH * DINNER];
__device__ __nv_bfloat16 g_xdh[MROWS * XPITCH],   g_xdl[MROWS * XPITCH];
__device__ __nv_bfloat16 g_Wdh[DINNER * DTRANK],  g_Wdl[DINNER * DTRANK];
__device__ __nv_bfloat16 g_yh[MROWS * DINNER],    g_yl[MROWS * DINNER];
__device__ __nv_bfloat16 g_Woh[DMODEL * DINNER],  g_Wol[DMODEL * DINNER];

// ===================== PTX helpers (sm_80+ only) ===========================
__device__ __forceinline__ uint32_t smem_u32(const void* p) {
    uint32_t a;
    asm("{ .reg .u64 t; cvta.to.shared.u64 t, %1; cvt.u32.u64 %0, t; }"
        : "=r"(a) : "l"(p));
    return a;
}
__device__ __forceinline__ void ldsm_x4(uint32_t* r, uint32_t addr) {
    asm volatile("ldmatrix.sync.aligned.m8n8.x4.shared.b16 {%0,%1,%2,%3}, [%4];"
        : "=r"(r[0]), "=r"(r[1]), "=r"(r[2]), "=r"(r[3]) : "r"(addr));
}
__device__ __forceinline__ void mma16816(float* c, const uint32_t* a,
                                         const uint32_t* b) {
    asm volatile("mma.sync.aligned.m16n8k16.row.col.f32.bf16.bf16.f32 "
        "{%0,%1,%2,%3}, {%4,%5,%6,%7}, {%8,%9}, {%0,%1,%2,%3};"
        : "+f"(c[0]), "+f"(c[1]), "+f"(c[2]), "+f"(c[3])
        : "r"(a[0]), "r"(a[1]), "r"(a[2]), "r"(a[3]), "r"(b[0]), "r"(b[1]));
}
#define CPA16(dst, src) \
    asm volatile("cp.async.cg.shared.global [%0], [%1], 16;" \
                 :: "r"(dst), "l"(src) : "memory")
#define CPA4(dst, src) \
    asm volatile("cp.async.ca.shared.global [%0], [%1], 4;" \
                 :: "r"(dst), "l"(src) : "memory")
#define CP_COMMIT() asm volatile("cp.async.commit_group;" ::: "memory")

// ---------------------------------------------------------------------------
// Tensor-core GEMM on pre-split operands (3-term Markidis split).
// CTA tile 128x64, BK=32, 256 threads (8 warps: 4m x 2n, warptile 32x32).
// 2-stage cp.async double buffer. B fragments loaded via ldmatrix.x4
// (2 ni per instruction): 8 LDSM + 24 HMMA per k16 step.
// EPI: 0 = plain store, 1 = softplus(acc+bias) store, 2 = atomicAdd.
// ---------------------------------------------------------------------------
#define BMT   128
#define BNT   64
#define BKT   32
#define PITCH 40
#define A_PLANE 10240u   // 128*40*2 bytes
#define B_PLANE 5120u    // 64*40*2 bytes
#define GSMEM   61440    // 2 bufs * 2 planes * (A_PLANE + B_PLANE)

__device__ __forceinline__ void cpa_fill(
    uint32_t sAh, uint32_t sAl, uint32_t sBh, uint32_t sBl,
    const __nv_bfloat16* Ahi, const __nv_bfloat16* Alo, int lda,
    const __nv_bfloat16* Whi, const __nv_bfloat16* Wlo, int ldw,
    int row0, int col0, int k0, int tid)
{
#pragma unroll
    for (int it = 0; it < 2; it++) {
        int idx = it * 256 + tid;
        int r = idx >> 2, ch = idx & 3;
        const size_t aoff = (size_t)(row0 + r) * lda + k0 + ch * 8;
        const uint32_t sd = (uint32_t)(r * 80 + ch * 16);
        CPA16(sAh + sd, Ahi + aoff);
        CPA16(sAl + sd, Alo + aoff);
    }
    {
        int r = tid >> 2, ch = tid & 3;
        const size_t boff = (size_t)(col0 + r) * ldw + k0 + ch * 8;
        const uint32_t sd = (uint32_t)(r * 80 + ch * 16);
        CPA16(sBh + sd, Whi + boff);
        CPA16(sBl + sd, Wlo + boff);
    }
    CP_COMMIT();
}

template<int EPI>
__global__ __launch_bounds__(256, 2)
void gemm_mma(const __nv_bfloat16* __restrict__ Ahi,
              const __nv_bfloat16* __restrict__ Alo, int lda,
              const __nv_bfloat16* __restrict__ Whi,
              const __nv_bfloat16* __restrict__ Wlo, int ldw,
              const float* __restrict__ bias,
              float* __restrict__ C, int ldc, int K)
{
    extern __shared__ char smem[];
    const uint32_t sb = smem_u32(smem);
    const uint32_t aB[2][2] = {{sb, sb + A_PLANE},
                               {sb + 2 * A_PLANE, sb + 3 * A_PLANE}};
    const uint32_t bB[2][2] = {{sb + 4 * A_PLANE, sb + 4 * A_PLANE + B_PLANE},
                               {sb + 4 * A_PLANE + 2 * B_PLANE,
                                sb + 4 * A_PLANE + 3 * B_PLANE}};

    const int tid  = threadIdx.x;
    const int lane = tid & 31;
    const int wid  = tid >> 5;
    const int wm   = wid >> 1;           // 0..3
    const int wn   = wid & 1;            // 0..1
    const int row0 = blockIdx.y * BMT;
    const int col0 = blockIdx.x * BNT;
    const int kbase = blockIdx.z * K;    // split-K chunk base

    // A x4: lanes 0-15 rows of a 16-row block, k-halves by lane>>4
    const int a_r = lane & 15, a_k = (lane >> 4) << 3;
    // B x4 (2 ni per load): row = pair*16 + ((lane>>4)<<3) + (lane&7),
    //                       k   = ((lane>>3)&1)<<3
    const int b2_r = ((lane >> 4) << 3) + (lane & 7);
    const int b2_k = ((lane >> 3) & 1) << 3;

    float acc[2][4][4];
#pragma unroll
    for (int mi = 0; mi < 2; mi++)
#pragma unroll
        for (int ni = 0; ni < 4; ni++)
#pragma unroll
            for (int j = 0; j < 4; j++) acc[mi][ni][j] = 0.f;

    const int nit = K / BKT;
    cpa_fill(aB[0][0], aB[0][1], bB[0][0], bB[0][1],
             Ahi, Alo, lda, Whi, Wlo, ldw, row0, col0, kbase, tid);

    for (int c = 0; c < nit; c++) {
        const int cur = c & 1;
        if (c + 1 < nit) {
            cpa_fill(aB[cur ^ 1][0], aB[cur ^ 1][1], bB[cur ^ 1][0], bB[cur ^ 1][1],
                     Ahi, Alo, lda, Whi, Wlo, ldw, row0, col0,
                     kbase + (c + 1) * BKT, tid);
            asm volatile("cp.async.wait_group 1;" ::: "memory");
        } else {
            asm volatile("cp.async.wait_group 0;" ::: "memory");
        }
        __syncthreads();

#pragma unroll
        for (int s = 0; s < 2; s++) {
            uint32_t ah[2][4], al[2][4], bh[4][2], bl[4][2];
#pragma unroll
            for (int mi = 0; mi < 2; mi++) {
                uint32_t e = (uint32_t)((wm * 32 + mi * 16 + a_r) * PITCH
                                        + s * 16 + a_k) * 2u;
                ldsm_x4(ah[mi], aB[cur][0] + e);
                ldsm_x4(al[mi], aB[cur][1] + e);
            }
#pragma unroll
            for (int p = 0; p < 2; p++) {   // ni pair: covers ni=2p, 2p+1
                uint32_t e = (uint32_t)((wn * 32 + p * 16 + b2_r) * PITCH
                                        + s * 16 + b2_k) * 2u;
                uint32_t r4[4];
                ldsm_x4(r4, bB[cur][0] + e);
                bh[2 * p][0] = r4[0]; bh[2 * p][1] = r4[1];
                bh[2 * p + 1][0] = r4[2]; bh[2 * p + 1][1] = r4[3];
                ldsm_x4(r4, bB[cur][1] + e);
                bl[2 * p][0] = r4[0]; bl[2 * p][1] = r4[1];
                bl[2 * p + 1][0] = r4[2]; bl[2 * p + 1][1] = r4[3];
            }
            // term-grouped issue (accumulator reuse distance 8)
#pragma unroll
            for (int mi = 0; mi < 2; mi++)
#pragma unroll
                for (int ni = 0; ni < 4; ni++)
                    mma16816(acc[mi][ni], ah[mi], bh[ni]);
#pragma unroll
            for (int mi = 0; mi < 2; mi++)
#pragma unroll
                for (int ni = 0; ni < 4; ni++)
                    mma16816(acc[mi][ni], ah[mi], bl[ni]);
#pragma unroll
            for (int mi = 0; mi < 2; mi++)
#pragma unroll
                for (int ni = 0; ni < 4; ni++)
                    mma16816(acc[mi][ni], al[mi], bh[ni]);
        }
        __syncthreads();
    }

    // ---- epilogue ----
    const int cr = lane >> 2;
    const int cc = (lane & 3) * 2;
#pragma unroll
    for (int mi = 0; mi < 2; mi++) {
#pragma unroll
        for (int ni = 0; ni < 4; ni++) {
            int row = row0 + wm * 32 + mi * 16 + cr;
            int col = col0 + wn * 32 + ni * 8 + cc;
            float v[4] = {acc[mi][ni][0], acc[mi][ni][1],
                          acc[mi][ni][2], acc[mi][ni][3]};
            if (EPI == 1) {
#pragma unroll
                for (int j = 0; j < 4; j++) {
                    float t = v[j] + bias[col + (j & 1)];
                    v[j] = (t > 20.f) ? t : log1pf(__expf(t));
                }
            }
            if (EPI == 2) {
                atomicAdd(C + (size_t)row * ldc + col,           v[0]);
                atomicAdd(C + (size_t)row * ldc + col + 1,       v[1]);
                atomicAdd(C + (size_t)(row + 8) * ldc + col,     v[2]);
                atomicAdd(C + (size_t)(row + 8) * ldc + col + 1, v[3]);
            } else {
                *(float2*)(C + (size_t)row * ldc + col)       = make_float2(v[0], v[1]);
                *(float2*)(C + (size_t)(row + 8) * ldc + col) = make_float2(v[2], v[3]);
            }
        }
    }
}

// -------------------- zero-fill (graph-safe memset replacement) ------------
__global__ void zero_buf(float4* __restrict__ p, int n4)
{
    int i = blockIdx.x * blockDim.x + threadIdx.x;
    if (i < n4) p[i] = make_float4(0.f, 0.f, 0.f, 0.f);
}

// -------------------- fp32 -> bf16 hi/lo converters ------------------------
__global__ void cvt_hl(const float4* __restrict__ in,
                       __nv_bfloat162* __restrict__ hi,
                       __nv_bfloat162* __restrict__ lo, int n4)
{
    int i = blockIdx.x * blockDim.x + threadIdx.x;
    if (i >= n4) return;
    float4 v = in[i];
    float f[4] = {v.x, v.y, v.z, v.w};
    __nv_bfloat16 h[4], l[4];
#pragma unroll
    for (int j = 0; j < 4; j++) {
        h[j] = __float2bfloat16(f[j]);
        l[j] = __float2bfloat16(f[j] - __bfloat162float(h[j]));
    }
    hi[2 * i]     = __nv_bfloat162(h[0], h[1]);
    hi[2 * i + 1] = __nv_bfloat162(h[2], h[3]);
    lo[2 * i]     = __nv_bfloat162(l[0], l[1]);
    lo[2 * i + 1] = __nv_bfloat162(l[2], l[3]);
}

// W_x [96, 2048] -> padded [128, 2048] hi/lo (rows 96..127 zero)
__global__ void cvt_hl_pad_wx(const float* __restrict__ in,
                              __nv_bfloat162* __restrict__ hi,
                              __nv_bfloat162* __restrict__ lo)
{
    int i = blockIdx.x * blockDim.x + threadIdx.x;
    if (i >= XPITCH * DINNER / 4) return;
    int row = i >> 9;
    int col4 = (i & 511) << 2;
    float f[4] = {0.f, 0.f, 0.f, 0.f};
    if (row < 96) {
        float4 v = *(const float4*)(in + (size_t)row * DINNER + col4);
        f[0] = v.x; f[1] = v.y; f[2] = v.z; f[3] = v.w;
    }
    __nv_bfloat16 h[4], l[4];
#pragma unroll
    for (int j = 0; j < 4; j++) {
        h[j] = __float2bfloat16(f[j]);
        l[j] = __float2bfloat16(f[j] - __bfloat162float(h[j]));
    }
    hi[2 * i]     = __nv_bfloat162(h[0], h[1]);
    hi[2 * i + 1] = __nv_bfloat162(h[2], h[3]);
    lo[2 * i]     = __nv_bfloat162(l[0], l[1]);
    lo[2 * i + 1] = __nv_bfloat162(l[2], l[3]);
}

// -------------------- causal conv1d + SiLU + z gate (+ inline split) -------
__global__ void conv_silu_kernel(const float* __restrict__ Wc,   // [DINNER,4]
                                 const float* __restrict__ bc)   // [DINNER]
{
    int i = blockIdx.x * blockDim.x + threadIdx.x;      // over MROWS*DINNER
    if (i >= MROWS * DINNER) return;
    int d = i & (DINNER - 1);
    int m = i >> 11;                                    // b*SEQ + l
    int b = m >> 10;
    int l = m & (SEQ - 1);

    float acc = bc[d];
#pragma unroll
    for (int k = 0; k < DCONV; k++) {
        int lt = l - (DCONV - 1) + k;
        if (lt >= 0)
            acc = fmaf(Wc[d * DCONV + k],
                       g_xz[(size_t)((b << 10) + lt) * (2 * DINNER) + d], acc);
    }
    float xc = acc / (1.f + __expf(-acc));              // silu
    g_xconv[i] = xc;
    __nv_bfloat16 hb = __float2bfloat16(xc);
    g_xch[i] = hb;
    g_xcl[i] = __float2bfloat16(xc - __bfloat162float(hb));

    float zv = g_xz[(size_t)m * (2 * DINNER) + DINNER + d];
    g_zsilu[i] = zv / (1.f + __expf(-zv));
}

// ---------------------------------------------------------------------------
// Selective scan v2 — smem-staged, cp.async double-buffered.
// 256 CTAs x 256 threads. CTA owns 16 channels x 16 states.
// ---------------------------------------------------------------------------
#define SCH 16
#define STT 64
#define NSTAGE (SEQ / STT)   // 16
#define BCP 36               // padded B/C row (floats); 144 B = 9*16 (aligned)

__global__ __launch_bounds__(256)
void scan_kernel(const float* __restrict__ A_log,   // [DINNER,16]
                 const float* __restrict__ Dp)      // [DINNER]
{
    __shared__ alignas(16) float s_dt[2][SCH][STT];
    __shared__ alignas(16) float s_xc[2][SCH][STT];
    __shared__ alignas(16) float s_zs[2][SCH][STT];
    __shared__ alignas(16) float s_bc[2][STT][BCP];

    const int tid = threadIdx.x;
    const int c = tid >> 4;              // channel within CTA (0..15)
    const int n = tid & 15;              // state
    const int chg = blockIdx.x * SCH;    // global channel base (0..4095)
    const int b  = chg >> 11;
    const int d0 = chg & (DINNER - 1);
    const size_t mb = (size_t)b * SEQ;

    const float A  = -__expf(A_log[(d0 + c) * DSTATE + n]);
    const float Dv = Dp[d0 + c];

    const uint32_t u_dt = smem_u32(s_dt), u_xc = smem_u32(s_xc);
    const uint32_t u_zs = smem_u32(s_zs), u_bc = smem_u32(s_bc);

    auto fill = [&](int s, int t0) {
#pragma unroll
        for (int i = 0; i < 4; i++) {
            int idx = i * 256 + tid;
            int ch = idx >> 6, t = idx & 63;
            size_t g = (mb + t0 + t) * DINNER + d0 + ch;
            uint32_t so = (uint32_t)(((s * SCH + ch) * STT + t) * 4);
            CPA4(u_dt + so, g_dt + g);
            CPA4(u_xc + so, g_xconv + g);
            CPA4(u_zs + so, g_zsilu + g);
        }
#pragma unroll
        for (int i = 0; i < 2; i++) {
            int idx = i * 256 + tid;
            int t = idx >> 3, chk = idx & 7;
            const float* src = g_xdbl + (mb + t0 + t) * XPITCH + DTRANK + chk * 4;
            uint32_t dst = u_bc + (uint32_t)(((s * STT + t) * BCP + chk * 4) * 4);
            CPA16(dst, src);
        }
        CP_COMMIT();
    };

    fill(0, 0);
    float h = 0.f;

    for (int st = 0; st < NSTAGE; st++) {
        const int cur = st & 1;
        if (st + 1 < NSTAGE) {
            fill(cur ^ 1, (st + 1) * STT);
            asm volatile("cp.async.wait_group 1;" ::: "memory");
        } else {
            asm volatile("cp.async.wait_group 0;" ::: "memory");
        }
        __syncthreads();

        const int t0 = st * STT;
#pragma unroll 4
        for (int t = 0; t < STT; t++) {
            float dtv = s_dt[cur][c][t];
            float xv  = s_xc[cur][c][t];
            float Bv  = s_bc[cur][t][n];
            float Cv  = s_bc[cur][t][16 + n];
            h = __expf(dtv * A) * h + dtv * Bv * xv;
            float yv = h * Cv;
            yv += __shfl_xor_sync(0xffffffffu, yv, 1);
            yv += __shfl_xor_sync(0xffffffffu, yv, 2);
            yv += __shfl_xor_sync(0xffffffffu, yv, 4);
            yv += __shfl_xor_sync(0xffffffffu, yv, 8);
            if (n == 0) {
                float yo = (yv + xv * Dv) * s_zs[cur][c][t];
                __nv_bfloat16 hb = __float2bfloat16(yo);
                __nv_bfloat16 lb = __float2bfloat16(yo - __bfloat162float(hb));
                size_t o = (mb + t0 + t) * DINNER + d0 + c;
                g_yh[o] = hb;
                g_yl[o] = lb;
            }
        }
        __syncthreads();
    }
}

// -------------------- host launcher ----------------------------------------
extern "C" void kernel_launch(void* const* d_in, const int* in_sizes, int n_in,
                              void* d_out, int out_size)
{
    const float* x      = (const float*)d_in[0];
    const float* W_in   = (const float*)d_in[1];
    const float* W_conv = (const float*)d_in[2];
    const float* b_conv = (const float*)d_in[3];
    const float* W_x    = (const float*)d_in[4];
    const float* W_dt   = (const float*)d_in[5];
    const float* b_dt   = (const float*)d_in[6];
    const float* A_log  = (const float*)d_in[7];
    const float* Dp     = (const float*)d_in[8];
    const float* W_out  = (const float*)d_in[9];
    float* out = (float*)d_out;

    float *p_xz, *p_xdbl, *p_dt;
    cudaGetSymbolAddress((void**)&p_xz,   g_xz);
    cudaGetSymbolAddress((void**)&p_xdbl, g_xdbl);
    cudaGetSymbolAddress((void**)&p_dt,   g_dt);

    __nv_bfloat16 *xhi, *xlo, *Wih, *Wil, *xch, *xcl, *Wxh, *Wxl;
    __nv_bfloat16 *xdh, *xdl, *Wdh, *Wdl, *yh, *yl, *Woh, *Wol;
    cudaGetSymbolAddress((void**)&xhi, g_xhi); cudaGetSymbolAddress((void**)&xlo, g_xlo);
    cudaGetSymbolAddress((void**)&Wih, g_Wih); cudaGetSymbolAddress((void**)&Wil, g_Wil);
    cudaGetSymbolAddress((void**)&xch, g_xch); cudaGetSymbolAddress((void**)&xcl, g_xcl);
    cudaGetSymbolAddress((void**)&Wxh, g_Wxh); cudaGetSymbolAddress((void**)&Wxl, g_Wxl);
    cudaGetSymbolAddress((void**)&xdh, g_xdh); cudaGetSymbolAddress((void**)&xdl, g_xdl);
    cudaGetSymbolAddress((void**)&Wdh, g_Wdh); cudaGetSymbolAddress((void**)&Wdl, g_Wdl);
    cudaGetSymbolAddress((void**)&yh,  g_yh);  cudaGetSymbolAddress((void**)&yl,  g_yl);
    cudaGetSymbolAddress((void**)&Woh, g_Woh); cudaGetSymbolAddress((void**)&Wol, g_Wol);

    cudaFuncSetAttribute(gemm_mma<0>, cudaFuncAttributeMaxDynamicSharedMemorySize, GSMEM);
    cudaFuncSetAttribute(gemm_mma<1>, cudaFuncAttributeMaxDynamicSharedMemorySize, GSMEM);
    cudaFuncSetAttribute(gemm_mma<2>, cudaFuncAttributeMaxDynamicSharedMemorySize, GSMEM);

    const int CT = 256;
    #define CVT(src, dh, dl, n) \
        cvt_hl<<<((n) / 4 + CT - 1) / CT, CT>>>((const float4*)(src), \
            (__nv_bfloat162*)(dh), (__nv_bfloat162*)(dl), (n) / 4)

    // splits needed by GEMM1 (+pad)
    CVT(x,     xhi, xlo, MROWS * DMODEL);
    CVT(W_in,  Wih, Wil, 2 * DINNER * DMODEL);
    cvt_hl_pad_wx<<<(XPITCH * DINNER / 4 + CT - 1) / CT, CT>>>(
        W_x, (__nv_bfloat162*)Wxh, (__nv_bfloat162*)Wxl);

    // 3) xz = x @ W_in^T   [2048, 4096], K=1024
    {
        dim3 grid((2 * DINNER) / BNT, MROWS / BMT, 1);   // 64 x 16
        gemm_mma<0><<<grid, 256, GSMEM>>>(xhi, xlo, DMODEL, Wih, Wil, DMODEL,
                                          nullptr, p_xz, 2 * DINNER, DMODEL);
    }
    // remaining weight splits + xdbl zero (independent of GEMM1)
    CVT(W_dt,  Wdh, Wdl, DINNER * DTRANK);
    CVT(W_out, Woh, Wol, DMODEL * DINNER);
    zero_buf<<<(MROWS * XPITCH / 4 + CT - 1) / CT, CT>>>(
        (float4*)p_xdbl, MROWS * XPITCH / 4);

    // causal conv + silu + z gate (+ xconv hi/lo split fused)
    conv_silu_kernel<<<(MROWS * DINNER + CT - 1) / CT, CT>>>(W_conv, b_conv);

    // x_dbl = x_conv @ W_x^T   [2048, 128(pad)], K=2048, split-K=8 (atomics)
    {
        dim3 grid(XPITCH / BNT, MROWS / BMT, 8);         // 2 x 16 x 8
        gemm_mma<2><<<grid, 256, GSMEM>>>(xch, xcl, DINNER, Wxh, Wxl, DINNER,
                                          nullptr, p_xdbl, XPITCH, DINNER / 8);
    }
    CVT(p_xdbl, xdh, xdl, MROWS * XPITCH);

    // dt = softplus(x_dbl[:, :64] @ W_dt^T + b_dt)   [2048, 2048], K=64
    {
        dim3 grid(DINNER / BNT, MROWS / BMT, 1);         // 32 x 16
        gemm_mma<1><<<grid, 256, GSMEM>>>(xdh, xdl, XPITCH, Wdh, Wdl, DTRANK,
                                          b_dt, p_dt, DINNER, DTRANK);
    }
    // selective scan (+ skip + gate fused, emits bf16 hi/lo directly)
    scan_kernel<<<BATCH * DINNER / SCH, 256>>>(A_log, Dp);

    // out = gated @ W_out^T   [2048, 1024], K=2048
    {
        dim3 grid(DMODEL / BNT, MROWS / BMT, 1);         // 16 x 16
        gemm_mma<0><<<grid, 256, GSMEM>>>(yh, yl, DINNER, Woh, Wol, DINNER,
                                          nullptr, out, DMODEL, DINNER);
    }
    (void)in_sizes; (void)n_in; (void)out_size;
}